// round 8
// baseline (speedup 1.0000x reference)
#include <cuda_runtime.h>

#define N_NODES    100000
#define N_EDGES    3200000
#define NUM_GRAPHS 128
#define HID        64
#define IN_DIM     15
#define NBLK       ((N_NODES + 255) / 256)   // scan blocks
#define NPB        96                        // nodes per linear block

// ---------------- scratch (device globals; no allocation allowed) -----------
// hs: bf16x2 per (node, lane-pair). +1 zero pad row for OOB gather lanes.
__device__ __align__(16) unsigned g_hs[(N_NODES + 1) * 32];
__device__ __align__(16) float    g_aggA[N_NODES * HID];
__device__ __align__(16) float    g_aggB[N_NODES * HID];
__device__ int   g_csrc [N_EDGES];
__device__ int   g_edeg  [N_NODES];
__device__ int   g_pre   [N_NODES];
__device__ int   g_rowptr[N_NODES];
__device__ int   g_fill  [N_NODES];
__device__ int   g_bsum[NBLK];
__device__ int   g_boff[NBLK];
__device__ float g_dis[N_NODES];
__device__ float g_cnt[NUM_GRAPHS];
__device__ int   g_e32;
__device__ int   g_b32;

// ---------------- packed f32x2 helpers ---------------------------------------
__device__ __forceinline__ unsigned long long fma2(unsigned long long a,
                                                   unsigned long long b,
                                                   unsigned long long c) {
    unsigned long long d;
    asm("fma.rn.f32x2 %0, %1, %2, %3;" : "=l"(d) : "l"(a), "l"(b), "l"(c));
    return d;
}
__device__ __forceinline__ unsigned long long pack2(float x) {
    unsigned long long d;
    asm("mov.b64 %0, {%1, %1};" : "=l"(d) : "f"(x));
    return d;
}

// ---------------- init: zero degrees + pad row + dtype detection -------------
__global__ void gnn_init(const void* edges, const void* batch) {
    int v = blockIdx.x * blockDim.x + threadIdx.x;
    if (v < N_NODES) g_edeg[v] = 0;
    if (blockIdx.x == 0 && threadIdx.x < 32)
        g_hs[N_NODES * 32 + threadIdx.x] = 0u;
    if (blockIdx.x == gridDim.x - 1) {
        __shared__ int se, sb;
        if (threadIdx.x == 0) { se = 0; sb = 0; }
        __syncthreads();
        for (int i = threadIdx.x; i < 2048; i += 256) {
            long long vi = (long long)i * (N_EDGES / 2048);
            long long x = ((const long long*)edges)[vi];
            if (x < 0 || x >= N_NODES) { atomicOr(&se, 1); break; }
        }
        for (int i = threadIdx.x; i < 2048; i += 256) {
            long long vi = (long long)i * ((N_NODES / 2) / 2048);
            long long x = ((const long long*)batch)[vi];
            if (x < 0 || x >= NUM_GRAPHS) { atomicOr(&sb, 1); break; }
        }
        __syncthreads();
        if (threadIdx.x == 0) { g_e32 = se; g_b32 = sb; }
    }
}

__device__ __forceinline__ int batch_at(const void* batch, int v) {
    return g_b32 ? ((const int*)batch)[v] : (int)((const long long*)batch)[v];
}

// ---------------- degree count (4 edges/thread, int4 fast path) --------------
__global__ void gnn_deg_count(const void* __restrict__ edges) {
    int i = blockIdx.x * blockDim.x + threadIdx.x;
    if (i >= N_EDGES / 4) return;
    if (g_e32) {
        const int4* d4 = (const int4*)((const int*)edges + N_EDGES);
        int4 d = d4[i];
        atomicAdd(&g_edeg[d.x], 1);
        atomicAdd(&g_edeg[d.y], 1);
        atomicAdd(&g_edeg[d.z], 1);
        atomicAdd(&g_edeg[d.w], 1);
    } else {
        const long long* e = (const long long*)edges + N_EDGES;
#pragma unroll
        for (int t = 0; t < 4; t++)
            atomicAdd(&g_edeg[(int)e[i * 4 + t]], 1);
    }
}

// ---------------- scan1 (+ fused dis) -----------------------------------------
__global__ void gnn_scan1() {
    __shared__ int s[256];
    int t = threadIdx.x;
    int i = blockIdx.x * 256 + t;
    int dv = (i < N_NODES) ? g_edeg[i] : 0;
    s[t] = dv; __syncthreads();
    for (int off = 1; off < 256; off <<= 1) {
        int add = (t >= off) ? s[t - off] : 0;
        __syncthreads();
        s[t] += add;
        __syncthreads();
    }
    if (i < N_NODES) {
        g_pre[i] = s[t] - dv;
        g_dis[i] = rsqrtf((float)(dv + 1));   // + self loop
    }
    if (t == 255) g_bsum[blockIdx.x] = s[255];
}

__global__ void gnn_scan2() {
    __shared__ int s[512];
    int t = threadIdx.x;
    int v = (t < NBLK) ? g_bsum[t] : 0;
    s[t] = v; __syncthreads();
    for (int off = 1; off < 512; off <<= 1) {
        int add = (t >= off) ? s[t - off] : 0;
        __syncthreads();
        s[t] += add;
        __syncthreads();
    }
    if (t < NBLK) g_boff[t] = s[t] - v;
}

__global__ void gnn_scan3() {
    int i = blockIdx.x * blockDim.x + threadIdx.x;
    if (i < N_NODES) {
        g_rowptr[i] = g_pre[i] + g_boff[blockIdx.x];
        g_fill[i]   = 0;
    }
}

// ---------------- CSR fill (4 edges/thread) -----------------------------------
__global__ void gnn_csr_fill(const void* __restrict__ edges) {
    int i = blockIdx.x * blockDim.x + threadIdx.x;
    if (i >= N_EDGES / 4) return;
    int s0, s1, s2, s3, d0, d1, d2, d3;
    if (g_e32) {
        const int4* s4 = (const int4*)edges;
        const int4* d4 = (const int4*)((const int*)edges + N_EDGES);
        int4 s = s4[i]; int4 d = d4[i];
        s0 = s.x; s1 = s.y; s2 = s.z; s3 = s.w;
        d0 = d.x; d1 = d.y; d2 = d.z; d3 = d.w;
    } else {
        const long long* es = (const long long*)edges;
        s0 = (int)es[i*4]; s1 = (int)es[i*4+1]; s2 = (int)es[i*4+2]; s3 = (int)es[i*4+3];
        d0 = (int)es[N_EDGES+i*4]; d1 = (int)es[N_EDGES+i*4+1];
        d2 = (int)es[N_EDGES+i*4+2]; d3 = (int)es[N_EDGES+i*4+3];
    }
    g_csrc[g_rowptr[d0] + atomicAdd(&g_fill[d0], 1)] = s0;
    g_csrc[g_rowptr[d1] + atomicAdd(&g_fill[d1], 1)] = s1;
    g_csrc[g_rowptr[d2] + atomicAdd(&g_fill[d2], 1)] = s2;
    g_csrc[g_rowptr[d3] + atomicAdd(&g_fill[d3], 1)] = s3;
}

// ---------------- linear: hs[v] = bf16((relu(in+b) @ W) * dis[v]) ------------
// 256 threads, 96 nodes/block, 3 nodes/thread, 8 cols/thread, f32x2 packed FMA.
template <int K, bool PRE>
__global__ void __launch_bounds__(256) gnn_linear(const float* __restrict__ in,
                                                  const float* __restrict__ W,
                                                  const float* __restrict__ bias_prev,
                                                  unsigned* __restrict__ hs) {
    constexpr int SR = (K + 3) & ~3;   // row stride (16B-aligned rows)
    constexpr int K4 = K / 4;
    __shared__ float Wsh[K * HID];
    __shared__ float insh[NPB * SR];
    const int tid  = threadIdx.x;
    const int base = blockIdx.x * NPB;

    for (int i = tid; i < K * HID; i += 256) Wsh[i] = W[i];
    for (int i = tid; i < NPB * K; i += 256) {
        int n = i / K;
        int k = i - n * K;
        int v = base + n;
        float val = 0.0f;
        if (v < N_NODES) {
            val = in[v * K + k];
            if (PRE) val = fmaxf(val + bias_prev[k], 0.0f);
        }
        insh[n * SR + k] = val;
    }
    __syncthreads();

    const int ng = tid >> 3;          // 0..31, 3 nodes each
    const int cb = (tid & 7) * 8;     // col block (8 cols = 4 packed pairs)
    unsigned long long accp[3][4];
#pragma unroll
    for (int i = 0; i < 3; i++)
#pragma unroll
        for (int j = 0; j < 4; j++) accp[i][j] = 0ull;

#pragma unroll
    for (int k4 = 0; k4 < K4; k4++) {
        float4 a0 = *(const float4*)&insh[(ng * 3 + 0) * SR + k4 * 4];
        float4 a1 = *(const float4*)&insh[(ng * 3 + 1) * SR + k4 * 4];
        float4 a2 = *(const float4*)&insh[(ng * 3 + 2) * SR + k4 * 4];
#pragma unroll
        for (int t = 0; t < 4; t++) {
            int k = k4 * 4 + t;
            ulonglong2 w0 = *(const ulonglong2*)&Wsh[k * HID + cb];
            ulonglong2 w1 = *(const ulonglong2*)&Wsh[k * HID + cb + 4];
            float av0 = (t == 0) ? a0.x : (t == 1) ? a0.y : (t == 2) ? a0.z : a0.w;
            float av1 = (t == 0) ? a1.x : (t == 1) ? a1.y : (t == 2) ? a1.z : a1.w;
            float av2 = (t == 0) ? a2.x : (t == 1) ? a2.y : (t == 2) ? a2.z : a2.w;
            unsigned long long p0 = pack2(av0), p1 = pack2(av1), p2 = pack2(av2);
            accp[0][0] = fma2(p0, w0.x, accp[0][0]);
            accp[0][1] = fma2(p0, w0.y, accp[0][1]);
            accp[0][2] = fma2(p0, w1.x, accp[0][2]);
            accp[0][3] = fma2(p0, w1.y, accp[0][3]);
            accp[1][0] = fma2(p1, w0.x, accp[1][0]);
            accp[1][1] = fma2(p1, w0.y, accp[1][1]);
            accp[1][2] = fma2(p1, w1.x, accp[1][2]);
            accp[1][3] = fma2(p1, w1.y, accp[1][3]);
            accp[2][0] = fma2(p2, w0.x, accp[2][0]);
            accp[2][1] = fma2(p2, w0.y, accp[2][1]);
            accp[2][2] = fma2(p2, w1.x, accp[2][2]);
            accp[2][3] = fma2(p2, w1.y, accp[2][3]);
        }
    }
#pragma unroll
    for (int k = K4 * 4; k < K; k++) {   // K tail (K=15)
        ulonglong2 w0 = *(const ulonglong2*)&Wsh[k * HID + cb];
        ulonglong2 w1 = *(const ulonglong2*)&Wsh[k * HID + cb + 4];
#pragma unroll
        for (int i = 0; i < 3; i++) {
            unsigned long long p = pack2(insh[(ng * 3 + i) * SR + k]);
            accp[i][0] = fma2(p, w0.x, accp[i][0]);
            accp[i][1] = fma2(p, w0.y, accp[i][1]);
            accp[i][2] = fma2(p, w1.x, accp[i][2]);
            accp[i][3] = fma2(p, w1.y, accp[i][3]);
        }
    }

#pragma unroll
    for (int i = 0; i < 3; i++) {
        int v = base + ng * 3 + i;
        if (v < N_NODES) {
            float ds = g_dis[v];
#pragma unroll
            for (int j = 0; j < 4; j++) {
                unsigned long long p = accp[i][j];
                float fl = __uint_as_float((unsigned)(p & 0xffffffffull)) * ds;
                float fh = __uint_as_float((unsigned)(p >> 32)) * ds;
                unsigned r;
                asm("cvt.rn.bf16x2.f32 %0, %1, %2;" : "=r"(r) : "f"(fh), "f"(fl));
                hs[v * 32 + (cb >> 1) + j] = r;
            }
        }
    }
}

// ---------------- gather: agg[v] = dis[v] * (sum_e hs[src] + hs[v]) ----------
// One warp per node, lane owns 2 cols (bf16x2). Per 32-chunk: one coalesced
// lane-load of indices, then unrolled SHFL+gather with a WARP-UNIFORM guard
// (j < n_in) so rows execute only deg iterations (uniform early exit) while
// keeping batched-load MLP inside the chunk. FINAL fuses bias+relu+mean-pool.
template <bool FINAL>
__global__ void __launch_bounds__(256) gnn_gather(const unsigned* __restrict__ hs,
                                                  float2* __restrict__ agg2,
                                                  const float2* __restrict__ bias2,
                                                  const void* __restrict__ batch,
                                                  float* __restrict__ out) {
    int warp = (blockIdx.x * blockDim.x + threadIdx.x) >> 5;
    int lane = threadIdx.x & 31;
    if (warp >= N_NODES) return;
    const int v   = warp;
    const int beg = g_rowptr[v];
    const int end = beg + g_edeg[v];

    unsigned h = hs[v * 32 + lane];   // self term
    float ax = __uint_as_float(h << 16);
    float ay = __uint_as_float(h & 0xffff0000u);

    for (int base = beg; base < end; base += 32) {
        int idx = base + lane;
        int s = (idx < end) ? g_csrc[idx] : N_NODES;  // pad row if OOB
        const int n_in = min(32, end - base);          // warp-uniform
#pragma unroll
        for (int j = 0; j < 32; j++) {
            if (j < n_in) {
                int ss = __shfl_sync(0xffffffffu, s, j);
                unsigned hh = hs[ss * 32 + lane];
                ax += __uint_as_float(hh << 16);
                ay += __uint_as_float(hh & 0xffff0000u);
            }
        }
    }
    float ds = g_dis[v];
    ax *= ds; ay *= ds;

    if (!FINAL) {
        agg2[v * 32 + lane] = make_float2(ax, ay);
    } else {
        int g = batch_at(batch, v);
        float2 b = bias2[lane];
        ax = fmaxf(ax + b.x, 0.0f);
        ay = fmaxf(ay + b.y, 0.0f);
        float* p = &out[g * HID + lane * 2];
        asm volatile("red.global.add.f32 [%0], %1;" :: "l"(p),     "f"(ax) : "memory");
        asm volatile("red.global.add.f32 [%0], %1;" :: "l"(p + 1), "f"(ay) : "memory");
        if (lane == 0) atomicAdd(&g_cnt[g], 1.0f);
    }
}

// ---------------- pooling epilogue -------------------------------------------
__global__ void gnn_zero_out(float* __restrict__ out) {
    int i = blockIdx.x * blockDim.x + threadIdx.x;
    if (i < NUM_GRAPHS * HID) out[i] = 0.0f;
    if (i < NUM_GRAPHS) g_cnt[i] = 0.0f;
}

__global__ void gnn_div(float* __restrict__ out) {
    int i = blockIdx.x * blockDim.x + threadIdx.x;
    if (i < NUM_GRAPHS * HID) {
        int g = i >> 6;
        out[i] /= fmaxf(g_cnt[g], 1.0f);
    }
}

// ---------------- host -------------------------------------------------------
extern "C" void kernel_launch(void* const* d_in, const int* in_sizes, int n_in,
                              void* d_out, int out_size) {
    const float* x     = (const float*)d_in[0];
    const float* w1    = (const float*)d_in[1];
    const float* b1    = (const float*)d_in[2];
    const float* w2    = (const float*)d_in[3];
    const float* b2    = (const float*)d_in[4];
    const float* w3    = (const float*)d_in[5];
    const float* b3    = (const float*)d_in[6];
    const float* w4    = (const float*)d_in[7];
    const float* b4    = (const float*)d_in[8];
    const void*  edges = d_in[9];
    const void*  batch = d_in[10];
    float* out = (float*)d_out;

    void *p_hs, *p_aggA, *p_aggB;
    cudaGetSymbolAddress(&p_hs,   g_hs);
    cudaGetSymbolAddress(&p_aggA, g_aggA);
    cudaGetSymbolAddress(&p_aggB, g_aggB);
    unsigned* hs   = (unsigned*)p_hs;
    float*    aggA = (float*)p_aggA;
    float*    aggB = (float*)p_aggB;

    const int TB = 256;
    const int nodeB  = (N_NODES + TB - 1) / TB;
    const int edge4B = (N_EDGES / 4 + TB - 1) / TB;

    gnn_init     <<<nodeB, TB>>>(edges, batch);
    gnn_deg_count<<<edge4B, TB>>>(edges);
    gnn_scan1    <<<NBLK, 256>>>();
    gnn_scan2    <<<1, 512>>>();
    gnn_scan3    <<<NBLK, 256>>>();
    gnn_csr_fill <<<edge4B, TB>>>(edges);

    const int linB = (N_NODES + NPB - 1) / NPB;
    const int gatB = (N_NODES * 32 + TB - 1) / TB;

    // layer 1
    gnn_linear<IN_DIM, false><<<linB, TB>>>(x, w1, nullptr, hs);
    gnn_gather<false><<<gatB, TB>>>(hs, (float2*)aggA, nullptr, nullptr, nullptr);
    // layer 2
    gnn_linear<HID, true><<<linB, TB>>>(aggA, w2, b1, hs);
    gnn_gather<false><<<gatB, TB>>>(hs, (float2*)aggB, nullptr, nullptr, nullptr);
    // layer 3
    gnn_linear<HID, true><<<linB, TB>>>(aggB, w3, b2, hs);
    gnn_gather<false><<<gatB, TB>>>(hs, (float2*)aggA, nullptr, nullptr, nullptr);
    // layer 4 + fused bias/relu/mean-pool
    gnn_linear<HID, true><<<linB, TB>>>(aggA, w4, b3, hs);
    gnn_zero_out<<<(NUM_GRAPHS * HID + TB - 1) / TB, TB>>>(out);
    gnn_gather<true><<<gatB, TB>>>(hs, nullptr, (const float2*)b4, batch, out);
    gnn_div<<<(NUM_GRAPHS * HID + TB - 1) / TB, TB>>>(out);
}

// round 9
// speedup vs baseline: 1.0731x; 1.0731x over previous
#include <cuda_runtime.h>
#include <cuda_fp16.h>

#define N_NODES    100000
#define N_EDGES    3200000
#define NUM_GRAPHS 128
#define HID        64
#define IN_DIM     15
#define NBLK       ((N_NODES + 255) / 256)   // scan blocks
#define NPB        96                        // nodes per linear block

// ---------------- scratch (device globals; no allocation allowed) -----------
// +1 zero pad row: out-of-range gather lanes read it (stays zero forever).
__device__ __align__(16) __half2 g_hs[(N_NODES + 1) * 32];
__device__ __align__(16) float   g_aggA[N_NODES * HID];
__device__ __align__(16) float   g_aggB[N_NODES * HID];
__device__ int   g_csrc [N_EDGES];
__device__ int   g_edeg  [N_NODES];
__device__ int   g_pre   [N_NODES];
__device__ int   g_rowptr[N_NODES];
__device__ int   g_fill  [N_NODES];
__device__ int   g_bsum[NBLK];
__device__ int   g_boff[NBLK];
__device__ float g_dis[N_NODES];
__device__ float g_cnt[NUM_GRAPHS];
__device__ int   g_e32;
__device__ int   g_b32;

// ---------------- init: zero degrees + pad row + dtype detection -------------
__global__ void gnn_init(const void* edges, const void* batch) {
    int v = blockIdx.x * blockDim.x + threadIdx.x;
    if (v < N_NODES) g_edeg[v] = 0;
    if (blockIdx.x == 0 && threadIdx.x < 32)
        g_hs[N_NODES * 32 + threadIdx.x] = __floats2half2_rn(0.0f, 0.0f);
    if (blockIdx.x == gridDim.x - 1) {
        __shared__ int se, sb;
        if (threadIdx.x == 0) { se = 0; sb = 0; }
        __syncthreads();
        for (int i = threadIdx.x; i < 2048; i += 256) {
            long long vi = (long long)i * (N_EDGES / 2048);
            long long x = ((const long long*)edges)[vi];
            if (x < 0 || x >= N_NODES) { atomicOr(&se, 1); break; }
        }
        for (int i = threadIdx.x; i < 2048; i += 256) {
            long long vi = (long long)i * ((N_NODES / 2) / 2048);
            long long x = ((const long long*)batch)[vi];
            if (x < 0 || x >= NUM_GRAPHS) { atomicOr(&sb, 1); break; }
        }
        __syncthreads();
        if (threadIdx.x == 0) { g_e32 = se; g_b32 = sb; }
    }
}

__device__ __forceinline__ int batch_at(const void* batch, int v) {
    return g_b32 ? ((const int*)batch)[v] : (int)((const long long*)batch)[v];
}

// ---------------- degree count (4 edges/thread, int4 fast path) --------------
__global__ void gnn_deg_count(const void* __restrict__ edges) {
    int i = blockIdx.x * blockDim.x + threadIdx.x;
    if (i >= N_EDGES / 4) return;
    if (g_e32) {
        const int4* d4 = (const int4*)((const int*)edges + N_EDGES);
        int4 d = d4[i];
        atomicAdd(&g_edeg[d.x], 1);
        atomicAdd(&g_edeg[d.y], 1);
        atomicAdd(&g_edeg[d.z], 1);
        atomicAdd(&g_edeg[d.w], 1);
    } else {
        const long long* e = (const long long*)edges + N_EDGES;
#pragma unroll
        for (int t = 0; t < 4; t++)
            atomicAdd(&g_edeg[(int)e[i * 4 + t]], 1);
    }
}

// ---------------- scan1 (+ fused dis) -----------------------------------------
__global__ void gnn_scan1() {
    __shared__ int s[256];
    int t = threadIdx.x;
    int i = blockIdx.x * 256 + t;
    int dv = (i < N_NODES) ? g_edeg[i] : 0;
    s[t] = dv; __syncthreads();
    for (int off = 1; off < 256; off <<= 1) {
        int add = (t >= off) ? s[t - off] : 0;
        __syncthreads();
        s[t] += add;
        __syncthreads();
    }
    if (i < N_NODES) {
        g_pre[i] = s[t] - dv;
        g_dis[i] = rsqrtf((float)(dv + 1));   // + self loop
    }
    if (t == 255) g_bsum[blockIdx.x] = s[255];
}

__global__ void gnn_scan2() {
    __shared__ int s[512];
    int t = threadIdx.x;
    int v = (t < NBLK) ? g_bsum[t] : 0;
    s[t] = v; __syncthreads();
    for (int off = 1; off < 512; off <<= 1) {
        int add = (t >= off) ? s[t - off] : 0;
        __syncthreads();
        s[t] += add;
        __syncthreads();
    }
    if (t < NBLK) g_boff[t] = s[t] - v;
}

__global__ void gnn_scan3() {
    int i = blockIdx.x * blockDim.x + threadIdx.x;
    if (i < N_NODES) {
        g_rowptr[i] = g_pre[i] + g_boff[blockIdx.x];
        g_fill[i]   = 0;
    }
}

// ---------------- CSR fill (4 edges/thread) -----------------------------------
__global__ void gnn_csr_fill(const void* __restrict__ edges) {
    int i = blockIdx.x * blockDim.x + threadIdx.x;
    if (i >= N_EDGES / 4) return;
    int s0, s1, s2, s3, d0, d1, d2, d3;
    if (g_e32) {
        const int4* s4 = (const int4*)edges;
        const int4* d4 = (const int4*)((const int*)edges + N_EDGES);
        int4 s = s4[i]; int4 d = d4[i];
        s0 = s.x; s1 = s.y; s2 = s.z; s3 = s.w;
        d0 = d.x; d1 = d.y; d2 = d.z; d3 = d.w;
    } else {
        const long long* es = (const long long*)edges;
        s0 = (int)es[i*4]; s1 = (int)es[i*4+1]; s2 = (int)es[i*4+2]; s3 = (int)es[i*4+3];
        d0 = (int)es[N_EDGES+i*4]; d1 = (int)es[N_EDGES+i*4+1];
        d2 = (int)es[N_EDGES+i*4+2]; d3 = (int)es[N_EDGES+i*4+3];
    }
    g_csrc[g_rowptr[d0] + atomicAdd(&g_fill[d0], 1)] = s0;
    g_csrc[g_rowptr[d1] + atomicAdd(&g_fill[d1], 1)] = s1;
    g_csrc[g_rowptr[d2] + atomicAdd(&g_fill[d2], 1)] = s2;
    g_csrc[g_rowptr[d3] + atomicAdd(&g_fill[d3], 1)] = s3;
}

// ---------------- linear: hs[v] = fp16((relu(in+b) @ W) * dis[v]) ------------
// EXACT R5 structure: 256 threads, 96 nodes/block, 3 nodes/thread, 8 cols.
// insh transposed [k][node] stride 97 (conflict-free); W read as float4.
template <int K, bool PRE>
__global__ void __launch_bounds__(256) gnn_linear(const float* __restrict__ in,
                                                  const float* __restrict__ W,
                                                  const float* __restrict__ bias_prev,
                                                  __half2* __restrict__ hs) {
    __shared__ float Wsh[K * HID];
    __shared__ float insh[K * 97];
    __shared__ float bsh[K];
    const int tid  = threadIdx.x;
    const int base = blockIdx.x * NPB;

    for (int i = tid; i < K * HID; i += 256) Wsh[i] = W[i];
    if (PRE) for (int i = tid; i < K; i += 256) bsh[i] = bias_prev[i];
    __syncthreads();

    for (int i = tid; i < NPB * K; i += 256) {
        int n = i / K;
        int k = i - n * K;
        int v = base + n;
        float val = 0.0f;
        if (v < N_NODES) {
            val = in[v * K + k];
            if (PRE) val = fmaxf(val + bsh[k], 0.0f);
        }
        insh[k * 97 + n] = val;
    }
    __syncthreads();

    const int ng = tid >> 3;          // 0..31 node groups of 3
    const int cb = (tid & 7) * 8;     // col block
    float acc[3][8];
#pragma unroll
    for (int i = 0; i < 3; i++)
#pragma unroll
        for (int j = 0; j < 8; j++) acc[i][j] = 0.0f;

#pragma unroll 8
    for (int k = 0; k < K; k++) {
        float4 w0 = *(const float4*)&Wsh[k * HID + cb];
        float4 w1 = *(const float4*)&Wsh[k * HID + cb + 4];
#pragma unroll
        for (int i = 0; i < 3; i++) {
            float a = insh[k * 97 + ng * 3 + i];
            acc[i][0] = fmaf(a, w0.x, acc[i][0]);
            acc[i][1] = fmaf(a, w0.y, acc[i][1]);
            acc[i][2] = fmaf(a, w0.z, acc[i][2]);
            acc[i][3] = fmaf(a, w0.w, acc[i][3]);
            acc[i][4] = fmaf(a, w1.x, acc[i][4]);
            acc[i][5] = fmaf(a, w1.y, acc[i][5]);
            acc[i][6] = fmaf(a, w1.z, acc[i][6]);
            acc[i][7] = fmaf(a, w1.w, acc[i][7]);
        }
    }

#pragma unroll
    for (int i = 0; i < 3; i++) {
        int v = base + ng * 3 + i;
        if (v < N_NODES) {
            float ds = g_dis[v];
#pragma unroll
            for (int j = 0; j < 4; j++) {
                hs[v * 32 + (cb >> 1) + j] =
                    __floats2half2_rn(acc[i][2 * j] * ds, acc[i][2 * j + 1] * ds);
            }
        }
    }
}

// ---------------- gather: agg[v] = dis[v] * (sum_e hs[src] + hs[v]) ----------
// EXACT R5 structure (warp per node, coalesced 32-index load, unrolled SHFL
// loop with warp-uniform guard, pad row for OOB). FINAL fuses
// bias+relu+mean-pool via red.global.add.v2.f32.
template <bool FINAL>
__global__ void __launch_bounds__(256) gnn_gather(const __half2* __restrict__ hs,
                                                  float2* __restrict__ agg2,
                                                  const float2* __restrict__ bias2,
                                                  const void* __restrict__ batch,
                                                  float* __restrict__ out) {
    int warp = (blockIdx.x * blockDim.x + threadIdx.x) >> 5;
    int lane = threadIdx.x & 31;
    if (warp >= N_NODES) return;
    const int v   = warp;
    const int beg = g_rowptr[v];
    const int end = beg + g_edeg[v];

    float2 acc = __half22float2(hs[v * 32 + lane]);  // self term

    for (int base = beg; base < end; base += 32) {
        int idx = base + lane;
        int s = (idx < end) ? g_csrc[idx] : N_NODES;  // pad row if OOB
        const int n_in = min(32, end - base);          // warp-uniform
#pragma unroll
        for (int j = 0; j < 32; j++) {
            if (j < n_in) {
                int ss = __shfl_sync(0xffffffffu, s, j);
                float2 hh = __half22float2(hs[ss * 32 + lane]);
                acc.x += hh.x;
                acc.y += hh.y;
            }
        }
    }
    float ds = g_dis[v];
    acc.x *= ds; acc.y *= ds;

    if (!FINAL) {
        agg2[v * 32 + lane] = acc;
    } else {
        int g = batch_at(batch, v);
        float2 b = bias2[lane];
        float x0 = fmaxf(acc.x + b.x, 0.0f);
        float x1 = fmaxf(acc.y + b.y, 0.0f);
        float* p = &out[g * HID + lane * 2];
        asm volatile("red.global.add.v2.f32 [%0], {%1, %2};"
                     :: "l"(p), "f"(x0), "f"(x1) : "memory");
        if (lane == 0) atomicAdd(&g_cnt[g], 1.0f);
    }
}

// ---------------- pooling epilogue -------------------------------------------
__global__ void gnn_zero_out(float* __restrict__ out) {
    int i = blockIdx.x * blockDim.x + threadIdx.x;
    if (i < NUM_GRAPHS * HID) out[i] = 0.0f;
    if (i < NUM_GRAPHS) g_cnt[i] = 0.0f;
}

__global__ void gnn_div(float* __restrict__ out) {
    int i = blockIdx.x * blockDim.x + threadIdx.x;
    if (i < NUM_GRAPHS * HID) {
        int g = i >> 6;
        out[i] /= fmaxf(g_cnt[g], 1.0f);
    }
}

// ---------------- host -------------------------------------------------------
extern "C" void kernel_launch(void* const* d_in, const int* in_sizes, int n_in,
                              void* d_out, int out_size) {
    const float* x     = (const float*)d_in[0];
    const float* w1    = (const float*)d_in[1];
    const float* b1    = (const float*)d_in[2];
    const float* w2    = (const float*)d_in[3];
    const float* b2    = (const float*)d_in[4];
    const float* w3    = (const float*)d_in[5];
    const float* b3    = (const float*)d_in[6];
    const float* w4    = (const float*)d_in[7];
    const float* b4    = (const float*)d_in[8];
    const void*  edges = d_in[9];
    const void*  batch = d_in[10];
    float* out = (float*)d_out;

    void *p_hs, *p_aggA, *p_aggB;
    cudaGetSymbolAddress(&p_hs,   g_hs);
    cudaGetSymbolAddress(&p_aggA, g_aggA);
    cudaGetSymbolAddress(&p_aggB, g_aggB);
    __half2* hs   = (__half2*)p_hs;
    float*   aggA = (float*)p_aggA;
    float*   aggB = (float*)p_aggB;

    const int TB = 256;
    const int nodeB  = (N_NODES + TB - 1) / TB;
    const int edge4B = (N_EDGES / 4 + TB - 1) / TB;

    gnn_init     <<<nodeB, TB>>>(edges, batch);
    gnn_deg_count<<<edge4B, TB>>>(edges);
    gnn_scan1    <<<NBLK, 256>>>();
    gnn_scan2    <<<1, 512>>>();
    gnn_scan3    <<<NBLK, 256>>>();
    gnn_csr_fill <<<edge4B, TB>>>(edges);

    const int linB = (N_NODES + NPB - 1) / NPB;
    const int gatB = (N_NODES * 32 + TB - 1) / TB;

    // layer 1
    gnn_linear<IN_DIM, false><<<linB, TB>>>(x, w1, nullptr, hs);
    gnn_gather<false><<<gatB, TB>>>(hs, (float2*)aggA, nullptr, nullptr, nullptr);
    // layer 2
    gnn_linear<HID, true><<<linB, TB>>>(aggA, w2, b1, hs);
    gnn_gather<false><<<gatB, TB>>>(hs, (float2*)aggB, nullptr, nullptr, nullptr);
    // layer 3
    gnn_linear<HID, true><<<linB, TB>>>(aggB, w3, b2, hs);
    gnn_gather<false><<<gatB, TB>>>(hs, (float2*)aggA, nullptr, nullptr, nullptr);
    // layer 4 + fused bias/relu/mean-pool
    gnn_linear<HID, true><<<linB, TB>>>(aggA, w4, b3, hs);
    gnn_zero_out<<<(NUM_GRAPHS * HID + TB - 1) / TB, TB>>>(out);
    gnn_gather<true><<<gatB, TB>>>(hs, nullptr, (const float2*)b4, batch, out);
    gnn_div<<<(NUM_GRAPHS * HID + TB - 1) / TB, TB>>>(out);
}

// round 10
// speedup vs baseline: 1.3406x; 1.2493x over previous
#include <cuda_runtime.h>
#include <cuda_fp16.h>

#define N_NODES    100000
#define N_EDGES    3200000
#define NUM_GRAPHS 128
#define HID        64
#define IN_DIM     15
#define NBLK       ((N_NODES + 255) / 256)   // scan blocks
#define NPB        96                        // nodes per linear block

// ---------------- scratch (device globals; no allocation allowed) -----------
// +1 zero pad row: out-of-range gather lanes read it (stays zero forever).
__device__ __align__(16) __half2 g_hs[(N_NODES + 1) * 32];
__device__ __align__(16) float   g_aggA[N_NODES * HID];
__device__ __align__(16) float   g_aggB[N_NODES * HID];
__device__ int   g_csrc [N_EDGES];   // CSR (by dst): source node per slot
__device__ int   g_edeg  [N_NODES];
__device__ int   g_pre   [N_NODES];
__device__ int   g_rowptr[N_NODES];
__device__ int   g_fill  [N_NODES];
__device__ int   g_bsum[NBLK];
__device__ int   g_boff[NBLK];
__device__ float g_dis[N_NODES];
__device__ float g_cnt[NUM_GRAPHS];
__device__ int   g_e32;
__device__ int   g_b32;

// ---------------- dtype detection -------------------------------------------
__global__ void gnn_detect(const void* edges, const void* batch) {
    __shared__ int se, sb;
    if (threadIdx.x == 0) { se = 0; sb = 0; }
    __syncthreads();
    for (int i = threadIdx.x; i < 2048; i += 256) {
        long long vi = (long long)i * (N_EDGES / 2048);
        long long v = ((const long long*)edges)[vi];
        if (v < 0 || v >= N_NODES) { atomicOr(&se, 1); break; }
    }
    for (int i = threadIdx.x; i < 2048; i += 256) {
        long long vi = (long long)i * ((N_NODES / 2) / 2048);
        long long v = ((const long long*)batch)[vi];
        if (v < 0 || v >= NUM_GRAPHS) { atomicOr(&sb, 1); break; }
    }
    __syncthreads();
    if (threadIdx.x == 0) { g_e32 = se; g_b32 = sb; }
}

__device__ __forceinline__ int edge_at(const void* edges, long long i) {
    return g_e32 ? ((const int*)edges)[i] : (int)((const long long*)edges)[i];
}
__device__ __forceinline__ int batch_at(const void* batch, int v) {
    return g_b32 ? ((const int*)batch)[v] : (int)((const long long*)batch)[v];
}

// ---------------- degree / normalization ------------------------------------
__global__ void gnn_deg_zero() {
    int v = blockIdx.x * blockDim.x + threadIdx.x;
    if (v < N_NODES) g_edeg[v] = 0;
    if (blockIdx.x == 0 && threadIdx.x < 32)   // zero the gather pad row
        g_hs[N_NODES * 32 + threadIdx.x] = __floats2half2_rn(0.0f, 0.0f);
}

__global__ void gnn_deg_count(const void* __restrict__ edges) {
    int e = blockIdx.x * blockDim.x + threadIdx.x;
    if (e < N_EDGES) {
        int d = edge_at(edges, (long long)N_EDGES + e);
        atomicAdd(&g_edeg[d], 1);
    }
}

__global__ void gnn_dis() {
    int v = blockIdx.x * blockDim.x + threadIdx.x;
    if (v < N_NODES) {
        float d = (float)(g_edeg[v] + 1);  // + self loop
        g_dis[v] = rsqrtf(d);
    }
}

// ---------------- exclusive scan of g_edeg -> g_rowptr -----------------------
__global__ void gnn_scan1() {
    __shared__ int s[256];
    int t = threadIdx.x;
    int i = blockIdx.x * 256 + t;
    int v = (i < N_NODES) ? g_edeg[i] : 0;
    s[t] = v; __syncthreads();
    for (int off = 1; off < 256; off <<= 1) {
        int add = (t >= off) ? s[t - off] : 0;
        __syncthreads();
        s[t] += add;
        __syncthreads();
    }
    if (i < N_NODES) g_pre[i] = s[t] - v;
    if (t == 255) g_bsum[blockIdx.x] = s[255];
}

__global__ void gnn_scan2() {
    __shared__ int s[512];
    int t = threadIdx.x;
    int v = (t < NBLK) ? g_bsum[t] : 0;
    s[t] = v; __syncthreads();
    for (int off = 1; off < 512; off <<= 1) {
        int add = (t >= off) ? s[t - off] : 0;
        __syncthreads();
        s[t] += add;
        __syncthreads();
    }
    if (t < NBLK) g_boff[t] = s[t] - v;
}

__global__ void gnn_scan3() {
    int i = blockIdx.x * blockDim.x + threadIdx.x;
    if (i < N_NODES) {
        g_rowptr[i] = g_pre[i] + g_boff[blockIdx.x];
        g_fill[i]   = 0;
    }
}

// ---------------- CSR fill ----------------------------------------------------
__global__ void gnn_csr_fill(const void* __restrict__ edges) {
    int e = blockIdx.x * blockDim.x + threadIdx.x;
    if (e < N_EDGES) {
        int s = edge_at(edges, e);
        int d = edge_at(edges, (long long)N_EDGES + e);
        int slot = g_rowptr[d] + atomicAdd(&g_fill[d], 1);
        g_csrc[slot] = s;
    }
}

// ---------------- linear: hs[v] = (relu(in+b_prev) @ W) * dis[v], fp16 -------
// 256 threads, 96 nodes/block, 3 nodes per thread, 8 cols per thread.
// insh transposed [k][node] with stride 97 (conflict-free); W read as float4.
template <int K, bool PRE>
__global__ void __launch_bounds__(256) gnn_linear(const float* __restrict__ in,
                                                  const float* __restrict__ W,
                                                  const float* __restrict__ bias_prev,
                                                  __half2* __restrict__ hs) {
    __shared__ float Wsh[K * HID];
    __shared__ float insh[K * 97];
    __shared__ float bsh[K];
    const int tid  = threadIdx.x;
    const int base = blockIdx.x * NPB;

    for (int i = tid; i < K * HID; i += 256) Wsh[i] = W[i];
    if (PRE) for (int i = tid; i < K; i += 256) bsh[i] = bias_prev[i];
    __syncthreads();

    for (int i = tid; i < NPB * K; i += 256) {
        int n = i / K;
        int k = i - n * K;
        int v = base + n;
        float val = 0.0f;
        if (v < N_NODES) {
            val = in[v * K + k];
            if (PRE) val = fmaxf(val + bsh[k], 0.0f);
        }
        insh[k * 97 + n] = val;
    }
    __syncthreads();

    const int ng = tid >> 3;          // 0..31 node groups of 3
    const int cb = (tid & 7) * 8;     // col block
    float acc[3][8];
#pragma unroll
    for (int i = 0; i < 3; i++)
#pragma unroll
        for (int j = 0; j < 8; j++) acc[i][j] = 0.0f;

#pragma unroll 8
    for (int k = 0; k < K; k++) {
        float4 w0 = *(const float4*)&Wsh[k * HID + cb];
        float4 w1 = *(const float4*)&Wsh[k * HID + cb + 4];
#pragma unroll
        for (int i = 0; i < 3; i++) {
            float a = insh[k * 97 + ng * 3 + i];
            acc[i][0] = fmaf(a, w0.x, acc[i][0]);
            acc[i][1] = fmaf(a, w0.y, acc[i][1]);
            acc[i][2] = fmaf(a, w0.z, acc[i][2]);
            acc[i][3] = fmaf(a, w0.w, acc[i][3]);
            acc[i][4] = fmaf(a, w1.x, acc[i][4]);
            acc[i][5] = fmaf(a, w1.y, acc[i][5]);
            acc[i][6] = fmaf(a, w1.z, acc[i][6]);
            acc[i][7] = fmaf(a, w1.w, acc[i][7]);
        }
    }

#pragma unroll
    for (int i = 0; i < 3; i++) {
        int v = base + ng * 3 + i;
        if (v < N_NODES) {
            float ds = g_dis[v];
#pragma unroll
            for (int j = 0; j < 4; j++) {
                hs[v * 32 + (cb >> 1) + j] =
                    __floats2half2_rn(acc[i][2 * j] * ds, acc[i][2 * j + 1] * ds);
            }
        }
    }
}

// ---------------- gather: agg[v] = dis[v] * (sum_e hs[src] + hs[v]) ----------
// One warp per node, lane owns 2 cols. Branch-free inner loop: OOB lanes read
// the zero pad row (single hot line).
__global__ void __launch_bounds__(256) gnn_gather(const __half2* __restrict__ hs,
                                                  float2* __restrict__ agg2) {
    int warp = (blockIdx.x * blockDim.x + threadIdx.x) >> 5;
    int lane = threadIdx.x & 31;
    if (warp >= N_NODES) return;
    const int v   = warp;
    const int beg = g_rowptr[v];
    const int end = beg + g_edeg[v];

    float2 acc = __half22float2(hs[v * 32 + lane]);  // self term

    for (int base = beg; base < end; base += 32) {
        int idx = base + lane;
        int s = (idx < end) ? g_csrc[idx] : N_NODES;  // pad row if OOB
#pragma unroll
        for (int j = 0; j < 32; j++) {
            int ss = __shfl_sync(0xffffffffu, s, j);
            float2 hh = __half22float2(hs[ss * 32 + lane]);
            acc.x += hh.x;
            acc.y += hh.y;
        }
    }
    float ds = g_dis[v];
    agg2[v * 32 + lane] = make_float2(acc.x * ds, acc.y * ds);
}

// ---------------- pooling ----------------------------------------------------
__global__ void gnn_zero_out(float* __restrict__ out) {
    int i = blockIdx.x * blockDim.x + threadIdx.x;
    if (i < NUM_GRAPHS * HID) out[i] = 0.0f;
    if (i < NUM_GRAPHS) g_cnt[i] = 0.0f;
}

__global__ void gnn_pool(const float4* __restrict__ agg,
                         const float4* __restrict__ bias4,
                         const void* __restrict__ batch,
                         float* __restrict__ out) {
    unsigned idx = blockIdx.x * blockDim.x + threadIdx.x;
    int v = idx >> 4;
    int c = idx & 15;
    if (v >= N_NODES) return;
    int g = batch_at(batch, v);
    float4 a = agg[v * 16 + c];
    float4 b = bias4[c];
    float x0 = fmaxf(a.x + b.x, 0.0f);
    float x1 = fmaxf(a.y + b.y, 0.0f);
    float x2 = fmaxf(a.z + b.z, 0.0f);
    float x3 = fmaxf(a.w + b.w, 0.0f);
    float* p = &out[g * HID + c * 4];
    asm volatile("red.global.add.v4.f32 [%0], {%1, %2, %3, %4};"
                 :: "l"(p), "f"(x0), "f"(x1), "f"(x2), "f"(x3)
                 : "memory");
    if (c == 0) atomicAdd(&g_cnt[g], 1.0f);
}

__global__ void gnn_div(float* __restrict__ out) {
    int i = blockIdx.x * blockDim.x + threadIdx.x;
    if (i < NUM_GRAPHS * HID) {
        int g = i >> 6;
        out[i] /= fmaxf(g_cnt[g], 1.0f);
    }
}

// ---------------- host -------------------------------------------------------
extern "C" void kernel_launch(void* const* d_in, const int* in_sizes, int n_in,
                              void* d_out, int out_size) {
    const float* x     = (const float*)d_in[0];
    const float* w1    = (const float*)d_in[1];
    const float* b1    = (const float*)d_in[2];
    const float* w2    = (const float*)d_in[3];
    const float* b2    = (const float*)d_in[4];
    const float* w3    = (const float*)d_in[5];
    const float* b3    = (const float*)d_in[6];
    const float* w4    = (const float*)d_in[7];
    const float* b4    = (const float*)d_in[8];
    const void*  edges = d_in[9];
    const void*  batch = d_in[10];
    float* out = (float*)d_out;

    void *p_hs, *p_aggA, *p_aggB;
    cudaGetSymbolAddress(&p_hs,   g_hs);
    cudaGetSymbolAddress(&p_aggA, g_aggA);
    cudaGetSymbolAddress(&p_aggB, g_aggB);
    __half2* hs   = (__half2*)p_hs;
    float*   aggA = (float*)p_aggA;
    float*   aggB = (float*)p_aggB;

    const int TB = 256;
    const int nodeB = (N_NODES + TB - 1) / TB;
    const int edgeB = (N_EDGES + TB - 1) / TB;

    gnn_detect   <<<1, 256>>>(edges, batch);
    gnn_deg_zero <<<nodeB, TB>>>();
    gnn_deg_count<<<edgeB, TB>>>(edges);
    gnn_dis      <<<nodeB, TB>>>();
    gnn_scan1    <<<NBLK, 256>>>();
    gnn_scan2    <<<1, 512>>>();
    gnn_scan3    <<<NBLK, 256>>>();
    gnn_csr_fill <<<edgeB, TB>>>(edges);

    const int linB = (N_NODES + NPB - 1) / NPB;
    const int gatB = (N_NODES * 32 + TB - 1) / TB;

    // layer 1
    gnn_linear<IN_DIM, false><<<linB, TB>>>(x, w1, nullptr, hs);
    gnn_gather<<<gatB, TB>>>(hs, (float2*)aggA);
    // layer 2
    gnn_linear<HID, true><<<linB, TB>>>(aggA, w2, b1, hs);
    gnn_gather<<<gatB, TB>>>(hs, (float2*)aggB);
    // layer 3
    gnn_linear<HID, true><<<linB, TB>>>(aggB, w3, b2, hs);
    gnn_gather<<<gatB, TB>>>(hs, (float2*)aggA);
    // layer 4
    gnn_linear<HID, true><<<linB, TB>>>(aggA, w4, b3, hs);
    gnn_gather<<<gatB, TB>>>(hs, (float2*)aggB);

    // pooling
    gnn_zero_out<<<(NUM_GRAPHS * HID + TB - 1) / TB, TB>>>(out);
    const unsigned poolT = (unsigned)N_NODES * 16u;
    gnn_pool<<<(int)((poolT + TB - 1) / TB), TB>>>(
        (const float4*)aggB, (const float4*)b4, batch, out);
    gnn_div<<<(NUM_GRAPHS * HID + TB - 1) / TB, TB>>>(out);
}

// round 11
// speedup vs baseline: 1.3958x; 1.0412x over previous
#include <cuda_runtime.h>

#define N_NODES    100000
#define N_EDGES    3200000
#define NUM_GRAPHS 128
#define HID        64
#define IN_DIM     15
#define NBLK       ((N_NODES + 255) / 256)   // scan blocks
#define NPB        96                        // nodes per linear block

// ---------------- scratch (device globals; no allocation allowed) -----------
// hs: 32 x bf16x2 per node (64 cols). +1 zero pad row for OOB gather lanes.
__device__ __align__(16) unsigned g_hs[(N_NODES + 1) * 32];
__device__ __align__(16) float    g_aggA[N_NODES * HID];
__device__ __align__(16) float    g_aggB[N_NODES * HID];
__device__ int   g_csrc [N_EDGES];   // CSR (by dst): source node per slot
__device__ int   g_edeg  [N_NODES];
__device__ int   g_pre   [N_NODES];
__device__ int   g_rowptr[N_NODES];
__device__ int   g_fill  [N_NODES];
__device__ int   g_bsum[NBLK];
__device__ int   g_boff[NBLK];
__device__ float g_dis[N_NODES];
__device__ float g_cnt[NUM_GRAPHS];
__device__ int   g_e32;
__device__ int   g_b32;

// ---------------- dtype detection -------------------------------------------
__global__ void gnn_detect(const void* edges, const void* batch) {
    __shared__ int se, sb;
    if (threadIdx.x == 0) { se = 0; sb = 0; }
    __syncthreads();
    for (int i = threadIdx.x; i < 2048; i += 256) {
        long long vi = (long long)i * (N_EDGES / 2048);
        long long v = ((const long long*)edges)[vi];
        if (v < 0 || v >= N_NODES) { atomicOr(&se, 1); break; }
    }
    for (int i = threadIdx.x; i < 2048; i += 256) {
        long long vi = (long long)i * ((N_NODES / 2) / 2048);
        long long v = ((const long long*)batch)[vi];
        if (v < 0 || v >= NUM_GRAPHS) { atomicOr(&sb, 1); break; }
    }
    __syncthreads();
    if (threadIdx.x == 0) { g_e32 = se; g_b32 = sb; }
}

__device__ __forceinline__ int edge_at(const void* edges, long long i) {
    return g_e32 ? ((const int*)edges)[i] : (int)((const long long*)edges)[i];
}
__device__ __forceinline__ int batch_at(const void* batch, int v) {
    return g_b32 ? ((const int*)batch)[v] : (int)((const long long*)batch)[v];
}

// ---------------- degree / normalization ------------------------------------
__global__ void gnn_deg_zero() {
    int v = blockIdx.x * blockDim.x + threadIdx.x;
    if (v < N_NODES) g_edeg[v] = 0;
    if (blockIdx.x == 0 && threadIdx.x < 32)   // zero the gather pad row
        g_hs[N_NODES * 32 + threadIdx.x] = 0u;
}

__global__ void gnn_deg_count(const void* __restrict__ edges) {
    int e = blockIdx.x * blockDim.x + threadIdx.x;
    if (e < N_EDGES) {
        int d = edge_at(edges, (long long)N_EDGES + e);
        atomicAdd(&g_edeg[d], 1);
    }
}

__global__ void gnn_dis() {
    int v = blockIdx.x * blockDim.x + threadIdx.x;
    if (v < N_NODES) {
        float d = (float)(g_edeg[v] + 1);  // + self loop
        g_dis[v] = rsqrtf(d);
    }
}

// ---------------- exclusive scan of g_edeg -> g_rowptr -----------------------
__global__ void gnn_scan1() {
    __shared__ int s[256];
    int t = threadIdx.x;
    int i = blockIdx.x * 256 + t;
    int v = (i < N_NODES) ? g_edeg[i] : 0;
    s[t] = v; __syncthreads();
    for (int off = 1; off < 256; off <<= 1) {
        int add = (t >= off) ? s[t - off] : 0;
        __syncthreads();
        s[t] += add;
        __syncthreads();
    }
    if (i < N_NODES) g_pre[i] = s[t] - v;
    if (t == 255) g_bsum[blockIdx.x] = s[255];
}

__global__ void gnn_scan2() {
    __shared__ int s[512];
    int t = threadIdx.x;
    int v = (t < NBLK) ? g_bsum[t] : 0;
    s[t] = v; __syncthreads();
    for (int off = 1; off < 512; off <<= 1) {
        int add = (t >= off) ? s[t - off] : 0;
        __syncthreads();
        s[t] += add;
        __syncthreads();
    }
    if (t < NBLK) g_boff[t] = s[t] - v;
}

__global__ void gnn_scan3() {
    int i = blockIdx.x * blockDim.x + threadIdx.x;
    if (i < N_NODES) {
        g_rowptr[i] = g_pre[i] + g_boff[blockIdx.x];
        g_fill[i]   = 0;
    }
}

// ---------------- CSR fill ----------------------------------------------------
__global__ void gnn_csr_fill(const void* __restrict__ edges) {
    int e = blockIdx.x * blockDim.x + threadIdx.x;
    if (e < N_EDGES) {
        int s = edge_at(edges, e);
        int d = edge_at(edges, (long long)N_EDGES + e);
        int slot = g_rowptr[d] + atomicAdd(&g_fill[d], 1);
        g_csrc[slot] = s;
    }
}

// ---------------- linear: hs[v] = bf16((relu(in+b_prev) @ W) * dis[v]) -------
// EXACT R10 body (fp32 FMA, transposed smem); only the output pack is bf16x2.
template <int K, bool PRE>
__global__ void __launch_bounds__(256) gnn_linear(const float* __restrict__ in,
                                                  const float* __restrict__ W,
                                                  const float* __restrict__ bias_prev,
                                                  unsigned* __restrict__ hs) {
    __shared__ float Wsh[K * HID];
    __shared__ float insh[K * 97];
    __shared__ float bsh[K];
    const int tid  = threadIdx.x;
    const int base = blockIdx.x * NPB;

    for (int i = tid; i < K * HID; i += 256) Wsh[i] = W[i];
    if (PRE) for (int i = tid; i < K; i += 256) bsh[i] = bias_prev[i];
    __syncthreads();

    for (int i = tid; i < NPB * K; i += 256) {
        int n = i / K;
        int k = i - n * K;
        int v = base + n;
        float val = 0.0f;
        if (v < N_NODES) {
            val = in[v * K + k];
            if (PRE) val = fmaxf(val + bsh[k], 0.0f);
        }
        insh[k * 97 + n] = val;
    }
    __syncthreads();

    const int ng = tid >> 3;          // 0..31 node groups of 3
    const int cb = (tid & 7) * 8;     // col block
    float acc[3][8];
#pragma unroll
    for (int i = 0; i < 3; i++)
#pragma unroll
        for (int j = 0; j < 8; j++) acc[i][j] = 0.0f;

#pragma unroll 8
    for (int k = 0; k < K; k++) {
        float4 w0 = *(const float4*)&Wsh[k * HID + cb];
        float4 w1 = *(const float4*)&Wsh[k * HID + cb + 4];
#pragma unroll
        for (int i = 0; i < 3; i++) {
            float a = insh[k * 97 + ng * 3 + i];
            acc[i][0] = fmaf(a, w0.x, acc[i][0]);
            acc[i][1] = fmaf(a, w0.y, acc[i][1]);
            acc[i][2] = fmaf(a, w0.z, acc[i][2]);
            acc[i][3] = fmaf(a, w0.w, acc[i][3]);
            acc[i][4] = fmaf(a, w1.x, acc[i][4]);
            acc[i][5] = fmaf(a, w1.y, acc[i][5]);
            acc[i][6] = fmaf(a, w1.z, acc[i][6]);
            acc[i][7] = fmaf(a, w1.w, acc[i][7]);
        }
    }

#pragma unroll
    for (int i = 0; i < 3; i++) {
        int v = base + ng * 3 + i;
        if (v < N_NODES) {
            float ds = g_dis[v];
#pragma unroll
            for (int j = 0; j < 4; j++) {
                float fl = acc[i][2 * j]     * ds;   // even col -> low half
                float fh = acc[i][2 * j + 1] * ds;   // odd col  -> high half
                unsigned r;
                asm("cvt.rn.bf16x2.f32 %0, %1, %2;" : "=r"(r) : "f"(fh), "f"(fl));
                hs[v * 32 + (cb >> 1) + j] = r;
            }
        }
    }
}

// ---------------- gather: agg[v] = dis[v] * (sum_e hs[src] + hs[v]) ----------
// Warp per node; lanes split into 4 subgroups of 8, processing 4 edges per
// iteration. Each lane loads one uint4 (16B = cols 8p..8p+7 as bf16x2) of its
// subgroup's source row -> 1 LDG.128 + 1 SHFL per 4 edges. bf16 unpack is
// SHL/AND (alu pipe). Final shfl_xor combine across subgroups.
__global__ void __launch_bounds__(256) gnn_gather(const uint4* __restrict__ hs4,
                                                  float4* __restrict__ agg4) {
    int warp = (blockIdx.x * blockDim.x + threadIdx.x) >> 5;
    int lane = threadIdx.x & 31;
    if (warp >= N_NODES) return;
    const int v  = warp;
    const int sg = lane >> 3;   // subgroup 0..3 (edge slot within quad)
    const int p  = lane & 7;    // 16B-chunk position within row
    const int beg = g_rowptr[v];
    const int end = beg + g_edeg[v];

    float acc[8];
#pragma unroll
    for (int i = 0; i < 8; i++) acc[i] = 0.0f;

    // self term: only subgroup 0 accumulates row v (once)
    {
        uint4 hv = hs4[v * 8 + p];
        if (sg == 0) {
            acc[0] += __uint_as_float(hv.x << 16);
            acc[1] += __uint_as_float(hv.x & 0xffff0000u);
            acc[2] += __uint_as_float(hv.y << 16);
            acc[3] += __uint_as_float(hv.y & 0xffff0000u);
            acc[4] += __uint_as_float(hv.z << 16);
            acc[5] += __uint_as_float(hv.z & 0xffff0000u);
            acc[6] += __uint_as_float(hv.w << 16);
            acc[7] += __uint_as_float(hv.w & 0xffff0000u);
        }
    }

    for (int base = beg; base < end; base += 32) {
        int idx = base + lane;
        int s = (idx < end) ? g_csrc[idx] : N_NODES;   // pad row (zeros) if OOB
        const int iters = (min(32, end - base) + 3) >> 2;  // warp-uniform
#pragma unroll
        for (int j = 0; j < 8; j++) {
            if (j < iters) {
                int ss = __shfl_sync(0xffffffffu, s, j * 4 + sg);
                uint4 hh = hs4[ss * 8 + p];
                acc[0] += __uint_as_float(hh.x << 16);
                acc[1] += __uint_as_float(hh.x & 0xffff0000u);
                acc[2] += __uint_as_float(hh.y << 16);
                acc[3] += __uint_as_float(hh.y & 0xffff0000u);
                acc[4] += __uint_as_float(hh.z << 16);
                acc[5] += __uint_as_float(hh.z & 0xffff0000u);
                acc[6] += __uint_as_float(hh.w << 16);
                acc[7] += __uint_as_float(hh.w & 0xffff0000u);
            }
        }
    }

    // combine subgroups: butterfly over lanes 8 and 16 apart
#pragma unroll
    for (int i = 0; i < 8; i++) {
        acc[i] += __shfl_xor_sync(0xffffffffu, acc[i], 8);
        acc[i] += __shfl_xor_sync(0xffffffffu, acc[i], 16);
    }

    float ds = g_dis[v];
    if (sg == 0) {   // lanes 0..7 write cols 8p..8p+7
        float4 r0 = make_float4(acc[0] * ds, acc[1] * ds, acc[2] * ds, acc[3] * ds);
        float4 r1 = make_float4(acc[4] * ds, acc[5] * ds, acc[6] * ds, acc[7] * ds);
        agg4[v * 16 + p * 2]     = r0;
        agg4[v * 16 + p * 2 + 1] = r1;
    }
}

// ---------------- pooling ----------------------------------------------------
__global__ void gnn_zero_out(float* __restrict__ out) {
    int i = blockIdx.x * blockDim.x + threadIdx.x;
    if (i < NUM_GRAPHS * HID) out[i] = 0.0f;
    if (i < NUM_GRAPHS) g_cnt[i] = 0.0f;
}

__global__ void gnn_pool(const float4* __restrict__ agg,
                         const float4* __restrict__ bias4,
                         const void* __restrict__ batch,
                         float* __restrict__ out) {
    unsigned idx = blockIdx.x * blockDim.x + threadIdx.x;
    int v = idx >> 4;
    int c = idx & 15;
    if (v >= N_NODES) return;
    int g = batch_at(batch, v);
    float4 a = agg[v * 16 + c];
    float4 b = bias4[c];
    float x0 = fmaxf(a.x + b.x, 0.0f);
    float x1 = fmaxf(a.y + b.y, 0.0f);
    float x2 = fmaxf(a.z + b.z, 0.0f);
    float x3 = fmaxf(a.w + b.w, 0.0f);
    float* p = &out[g * HID + c * 4];
    asm volatile("red.global.add.v4.f32 [%0], {%1, %2, %3, %4};"
                 :: "l"(p), "f"(x0), "f"(x1), "f"(x2), "f"(x3)
                 : "memory");
    if (c == 0) atomicAdd(&g_cnt[g], 1.0f);
}

__global__ void gnn_div(float* __restrict__ out) {
    int i = blockIdx.x * blockDim.x + threadIdx.x;
    if (i < NUM_GRAPHS * HID) {
        int g = i >> 6;
        out[i] /= fmaxf(g_cnt[g], 1.0f);
    }
}

// ---------------- host -------------------------------------------------------
extern "C" void kernel_launch(void* const* d_in, const int* in_sizes, int n_in,
                              void* d_out, int out_size) {
    const float* x     = (const float*)d_in[0];
    const float* w1    = (const float*)d_in[1];
    const float* b1    = (const float*)d_in[2];
    const float* w2    = (const float*)d_in[3];
    const float* b2    = (const float*)d_in[4];
    const float* w3    = (const float*)d_in[5];
    const float* b3    = (const float*)d_in[6];
    const float* w4    = (const float*)d_in[7];
    const float* b4    = (const float*)d_in[8];
    const void*  edges = d_in[9];
    const void*  batch = d_in[10];
    float* out = (float*)d_out;

    void *p_hs, *p_aggA, *p_aggB;
    cudaGetSymbolAddress(&p_hs,   g_hs);
    cudaGetSymbolAddress(&p_aggA, g_aggA);
    cudaGetSymbolAddress(&p_aggB, g_aggB);
    unsigned* hs   = (unsigned*)p_hs;
    float*    aggA = (float*)p_aggA;
    float*    aggB = (float*)p_aggB;

    const int TB = 256;
    const int nodeB = (N_NODES + TB - 1) / TB;
    const int edgeB = (N_EDGES + TB - 1) / TB;

    gnn_detect   <<<1, 256>>>(edges, batch);
    gnn_deg_zero <<<nodeB, TB>>>();
    gnn_deg_count<<<edgeB, TB>>>(edges);
    gnn_dis      <<<nodeB, TB>>>();
    gnn_scan1    <<<NBLK, 256>>>();
    gnn_scan2    <<<1, 512>>>();
    gnn_scan3    <<<NBLK, 256>>>();
    gnn_csr_fill <<<edgeB, TB>>>(edges);

    const int linB = (N_NODES + NPB - 1) / NPB;
    const int gatB = (N_NODES * 32 + TB - 1) / TB;

    // layer 1
    gnn_linear<IN_DIM, false><<<linB, TB>>>(x, w1, nullptr, hs);
    gnn_gather<<<gatB, TB>>>((const uint4*)hs, (float4*)aggA);
    // layer 2
    gnn_linear<HID, true><<<linB, TB>>>(aggA, w2, b1, hs);
    gnn_gather<<<gatB, TB>>>((const uint4*)hs, (float4*)aggB);
    // layer 3
    gnn_linear<HID, true><<<linB, TB>>>(aggB, w3, b2, hs);
    gnn_gather<<<gatB, TB>>>((const uint4*)hs, (float4*)aggA);
    // layer 4
    gnn_linear<HID, true><<<linB, TB>>>(aggA, w4, b3, hs);
    gnn_gather<<<gatB, TB>>>((const uint4*)hs, (float4*)aggB);

    // pooling
    gnn_zero_out<<<(NUM_GRAPHS * HID + TB - 1) / TB, TB>>>(out);
    const unsigned poolT = (unsigned)N_NODES * 16u;
    gnn_pool<<<(int)((poolT + TB - 1) / TB), TB>>>(
        (const float4*)aggB, (const float4*)b4, batch, out);
    gnn_div<<<(NUM_GRAPHS * HID + TB - 1) / TB, TB>>>(out);
}